// round 17
// baseline (speedup 1.0000x reference)
#include <cuda_runtime.h>
#include <cuda_bf16.h>
#include <cstdint>

#define BB 128
#define NN 512
#define FF 128

// ---------------- device scratch (allocation-free rule) ----------------
// frag-linear hT: [b][k8 0..63][jj 0..7][gid 0..7][tq 0..3] float4
__device__ __align__(256) float4 g_hTf[(size_t)BB * 64 * 8 * 32];
// frag-linear W^T: [k8 0..15][jj 0..7][gid][tq] float4
__device__ __align__(256) float4 g_Wf[16 * 8 * 32];
__device__ float g_dnorm[BB * NN];

// ---------------- helpers ----------------
__device__ __forceinline__ uint32_t smem_u32(const void* p) {
    uint32_t r;
    asm("{ .reg .u64 t; cvta.to.shared.u64 t, %1; cvt.u32.u64 %0, t; }" : "=r"(r) : "l"(p));
    return r;
}
__device__ __forceinline__ void cp16(uint32_t dst, const void* src) {
    asm volatile("cp.async.cg.shared.global [%0], [%1], 16;" :: "r"(dst), "l"(src));
}
#define CP_COMMIT() asm volatile("cp.async.commit_group;" ::: "memory")
#define CP_WAIT_2() asm volatile("cp.async.wait_group 2;" ::: "memory")
#define CP_WAIT_1() asm volatile("cp.async.wait_group 1;" ::: "memory")
#define CP_WAIT_0() asm volatile("cp.async.wait_group 0;" ::: "memory")

__device__ __forceinline__ void lds128(uint32_t r[4], uint32_t a) {
    asm volatile("ld.shared.v4.u32 {%0,%1,%2,%3}, [%4];"
                 : "=r"(r[0]), "=r"(r[1]), "=r"(r[2]), "=r"(r[3]) : "r"(a));
}
__device__ __forceinline__ void ldsm4(uint32_t r[4], uint32_t addr) {
    asm volatile("ldmatrix.sync.aligned.m8n8.x4.shared.b16 {%0,%1,%2,%3}, [%4];"
                 : "=r"(r[0]), "=r"(r[1]), "=r"(r[2]), "=r"(r[3]) : "r"(addr));
}
__device__ __forceinline__ void sts64(uint32_t a, float x, float y) {
    asm volatile("st.shared.v2.f32 [%0], {%1, %2};" :: "r"(a), "f"(x), "f"(y));
}
__device__ __forceinline__ uint32_t rna(uint32_t x) {
    uint32_t y;
    asm("cvt.rna.tf32.f32 %0, %1;" : "=r"(y) : "r"(x));
    return y;
}
__device__ __forceinline__ float rna_f(float v) {
    return __uint_as_float(rna(__float_as_uint(v)));
}
__device__ __forceinline__ void mma_tf32(float c[4], const uint32_t a[4],
                                         uint32_t b0, uint32_t b1) {
    asm volatile(
        "mma.sync.aligned.m16n8k8.row.col.f32.tf32.tf32.f32 "
        "{%0,%1,%2,%3}, {%4,%5,%6,%7}, {%8,%9}, {%0,%1,%2,%3};"
        : "+f"(c[0]), "+f"(c[1]), "+f"(c[2]), "+f"(c[3])
        : "r"(a[0]), "r"(a[1]), "r"(a[2]), "r"(a[3]), "r"(b0), "r"(b1));
}

// ---------------- Kernel 1: degree -> dnorm ----------------
__global__ void deg_kernel(const float* __restrict__ adj) {
    int row  = blockIdx.x * 8 + (threadIdx.x >> 5);
    int lane = threadIdx.x & 31;
    const float4* p = (const float4*)(adj + (size_t)row * NN);
    float s = 0.f;
#pragma unroll
    for (int i = 0; i < 4; i++) {
        float4 v = p[lane + i * 32];
        s += (v.x + v.y) + (v.z + v.w);
    }
#pragma unroll
    for (int o = 16; o; o >>= 1) s += __shfl_xor_sync(0xffffffffu, s, o);
    if (lane == 0) g_dnorm[row] = (s > 0.f) ? rsqrtf(s) : 0.f;
}

// ---------------- Kernel 2: W -> frag-linear W^T, tf32-rounded ----------------
__global__ void prep_w_kernel(const float* __restrict__ W) {
    int idx = blockIdx.x * 256 + threadIdx.x;   // 16 blocks x 256 = 4096 float4s
    int k8 = idx >> 8, jj = (idx >> 5) & 7, gid = (idx >> 2) & 7, tq = idx & 3;
    int n0 = jj * 16 + gid, n1 = n0 + 8;
    int k = k8 * 8 + tq;
    float4 v;
    v.x = rna_f(W[k * FF + n0]);
    v.y = rna_f(W[(k + 4) * FF + n0]);
    v.z = rna_f(W[k * FF + n1]);
    v.w = rna_f(W[(k + 4) * FF + n1]);
    g_Wf[idx] = v;
}

// ---------------- Kernel 3: frag-linear h^T = (dnorm ⊙ x)^T, tf32-rounded ----------------
__global__ __launch_bounds__(256) void prep_h_kernel(const float* __restrict__ x) {
    __shared__ float s[64 * 132];
    int b  = blockIdx.x >> 3;
    int c8 = blockIdx.x & 7;          // 64-node chunk
    int k0 = c8 * 64;
    int tid = threadIdx.x;
    const float4* gx = (const float4*)(x + ((size_t)b * NN + k0) * FF);
#pragma unroll
    for (int i = 0; i < 8; i++) {
        int f = tid + i * 256;        // float4 idx in 64x128 tile
        int k = f >> 5, g4 = (f & 31) * 4;
        float4 v = gx[f];
        float dn = g_dnorm[b * NN + k0 + k];
        s[k * 132 + g4 + 0] = v.x * dn;
        s[k * 132 + g4 + 1] = v.y * dn;
        s[k * 132 + g4 + 2] = v.z * dn;
        s[k * 132 + g4 + 3] = v.w * dn;
    }
    __syncthreads();
    int jj = tid >> 5, gid = (tid >> 2) & 7, tq = tid & 3;
    int f0 = jj * 16 + gid, f1 = f0 + 8;
#pragma unroll
    for (int k8l = 0; k8l < 8; k8l++) {
        int kl = k8l * 8 + tq;
        float4 v;
        v.x = rna_f(s[kl * 132 + f0]);
        v.y = rna_f(s[(kl + 4) * 132 + f0]);
        v.z = rna_f(s[kl * 132 + f1]);
        v.w = rna_f(s[(kl + 4) * 132 + f1]);
        g_hTf[(((size_t)b * 64 + c8 * 8 + k8l) * 8 + jj) * 32 + gid * 4 + tq] = v;
    }
}

// ---------------- Fused: t = adj@h (tf32, K=512); out = relu(dn*(t@W)+b) ----------------
// 512 threads, warp grid 4x4, warp tile 32x32, frag double-buffered, ldmatrix A.
// smem phase 1: 4-stage ring x 34816 B (one barrier per stage):
//   A adj fp32 [128r x 32k, stride 144B] (18432 B) + B hT frags linear (16384 B)
// smem phase 2: A2 (t fp32) at 0, stride 528B (67584 B);
//   W frag half (32768 B) at 67584 (reloaded per k-half). Peak 100352 <= 139264.
#define STG 34816
#define BOFF 18432
#define ASTRIDE 144
#define A2STRIDE 528
#define WOFF2 67584
#define FUSED_SMEM (4 * STG)

__global__ __launch_bounds__(512)
void fused_kernel(const float* __restrict__ adj, const float* __restrict__ bias,
                  float* __restrict__ out) {
    extern __shared__ char sm[];
    uint32_t sbu = smem_u32(sm);
    int tid = threadIdx.x, lane = tid & 31, wid = tid >> 5;
    int warp_m = wid & 3, warp_n = wid >> 2;   // 4 x 4 warps, warp tile 32x32
    int gid = lane >> 2, tq = lane & 3;
    int bb = blockIdx.x >> 2, m0 = (blockIdx.x & 3) * 128;

    const char* adjb = (const char*)adj;
    const char* hfb = (const char*)g_hTf;
    const char* wfb = (const char*)g_Wf;

    // ldmatrix per-lane offsets: matrix mm = lane>>3 selects {row+8? , k+4?}
    int mm = lane >> 3, rowin = lane & 7;
    uint32_t aoff1[2], aoff2[2];
#pragma unroll
    for (int i = 0; i < 2; i++) {
        int r = warp_m * 32 + i * 16 + (mm & 1) * 8 + rowin;
        aoff1[i] = (uint32_t)(r * ASTRIDE + (mm >> 1) * 16);
        aoff2[i] = (uint32_t)(r * A2STRIDE + (mm >> 1) * 16);
    }

    auto load_stage = [&](int s) {
        uint32_t base = sbu + (s & 3) * STG;
#pragma unroll
        for (int i = 0; i < 2; i++) {                 // adj: 128 rows x 32 floats
            int c = tid + i * 512;                    // 0..1023
            int row = c >> 3, ch = c & 7;
            cp16(base + row * ASTRIDE + ch * 16,
                 adjb + ((size_t)(bb * NN + m0 + row) * NN + s * 32) * 4 + ch * 16);
        }
#pragma unroll
        for (int i = 0; i < 2; i++) {                 // hT frags: 16 KB linear
            int c = tid + i * 512;
            cp16(base + BOFF + c * 16,
                 hfb + ((size_t)(bb * 64 + s * 4)) * 4096 + c * 16);
        }
    };
    auto load_w_half = [&](int half) {
#pragma unroll
        for (int i = 0; i < 4; i++) {
            int c = tid + i * 512;                    // 0..2047 chunks, 32 KB
            cp16(sbu + WOFF2 + c * 16, wfb + (size_t)(half * 2048 + c) * 16);
        }
    };

    // fragment loaders (double-buffered)
    auto p1_loadB = [&](uint32_t base, int k8, uint32_t (&fb)[2][4]) {
        uint32_t a0 = base + BOFF + k8 * 4096 + (warp_n * 2) * 512 + gid * 64 + tq * 16;
        lds128(fb[0], a0);
        lds128(fb[1], a0 + 512);
    };
    auto p1_loadA = [&](uint32_t base, int k8, uint32_t (&fa)[2][4]) {
#pragma unroll
        for (int i = 0; i < 2; i++) {
            ldsm4(fa[i], base + aoff1[i] + k8 * 32);
            fa[i][0] = rna(fa[i][0]); fa[i][1] = rna(fa[i][1]);
            fa[i][2] = rna(fa[i][2]); fa[i][3] = rna(fa[i][3]);
        }
    };
    auto p2_loadW = [&](int kk, uint32_t (&fb)[2][4]) {
        uint32_t a0 = sbu + WOFF2 + (kk & 7) * 4096 + (warp_n * 2) * 512 + gid * 64 + tq * 16;
        lds128(fb[0], a0);
        lds128(fb[1], a0 + 512);
    };
    auto p2_loadA = [&](int k8, uint32_t (&fa)[2][4]) {
#pragma unroll
        for (int i = 0; i < 2; i++) {
            ldsm4(fa[i], sbu + aoff2[i] + k8 * 32);
            fa[i][0] = rna(fa[i][0]); fa[i][1] = rna(fa[i][1]);
            fa[i][2] = rna(fa[i][2]); fa[i][3] = rna(fa[i][3]);
        }
    };

    float C[2][4][4];
#pragma unroll
    for (int i = 0; i < 2; i++)
#pragma unroll
        for (int j = 0; j < 4; j++)
#pragma unroll
            for (int k = 0; k < 4; k++) C[i][j][k] = 0.f;

    auto do_mma = [&](uint32_t (&fa)[2][4], uint32_t (&fb)[2][4]) {
#pragma unroll
        for (int i = 0; i < 2; i++)
#pragma unroll
            for (int j = 0; j < 4; j++)
                mma_tf32(C[i][j], fa[i], fb[j >> 1][(j & 1) * 2], fb[j >> 1][(j & 1) * 2 + 1]);
    };

    load_stage(0); CP_COMMIT();
    load_stage(1); CP_COMMIT();
    load_stage(2); CP_COMMIT();

    uint32_t FA[2][2][4], FB[2][2][4];

    // ---- phase 1: t = adj @ h, K = 512; ONE barrier per stage (4-deep ring) ----
    for (int s = 0; s < 16; s++) {
        if (s < 14) { CP_WAIT_2(); } else if (s == 14) { CP_WAIT_1(); } else { CP_WAIT_0(); }
        __syncthreads();
        // buffer (s+3)&3 == (s-1)&3: its readers (stage s-1) all passed this barrier
        if (s + 3 < 16) { load_stage(s + 3); CP_COMMIT(); }
        uint32_t base = sbu + (s & 3) * STG;
        p1_loadB(base, 0, FB[0]);
        p1_loadA(base, 0, FA[0]);
#pragma unroll
        for (int k8 = 0; k8 < 4; k8++) {
            int cur = k8 & 1, nxt = cur ^ 1;
            if (k8 < 3) { p1_loadB(base, k8 + 1, FB[nxt]); p1_loadA(base, k8 + 1, FA[nxt]); }
            do_mma(FA[cur], FB[cur]);
        }
        // no trailing barrier: next stage's top barrier covers it
    }

    // ---- prefetch W frag half 0 (k8 0..7) ----
    // W slot overlaps ring bufs 1/2 tail regions; their last readers (stages 13/14)
    // all passed the stage-15 top barrier. Laggards are in stage-15 body (buf 3). Safe.
    load_w_half(0);
    CP_COMMIT();

    // ---- epilogue 1: C (= t tile) -> smem fp32 A2 (bufs 0/1 region); zero C ----
#pragma unroll
    for (int i = 0; i < 2; i++) {
        int r0 = warp_m * 32 + i * 16 + gid;
#pragma unroll
        for (int j = 0; j < 4; j++) {
            int cc = warp_n * 32 + j * 8 + tq * 2;
            sts64(sbu + r0 * A2STRIDE + cc * 4, C[i][j][0], C[i][j][1]);
            sts64(sbu + (r0 + 8) * A2STRIDE + cc * 4, C[i][j][2], C[i][j][3]);
            C[i][j][0] = C[i][j][1] = C[i][j][2] = C[i][j][3] = 0.f;
        }
    }
    CP_WAIT_0();
    __syncthreads();

    // ---- phase 2: out = t @ W (K = 128, two k8-halves; W frags reloaded between) ----
#pragma unroll 1
    for (int half = 0; half < 2; half++) {
        p2_loadW(0, FB[0]);
        p2_loadA(half * 8, FA[0]);
#pragma unroll
        for (int kk = 0; kk < 8; kk++) {
            int cur = kk & 1, nxt = cur ^ 1;
            if (kk < 7) { p2_loadW(kk + 1, FB[nxt]); p2_loadA(half * 8 + kk + 1, FA[nxt]); }
            do_mma(FA[cur], FB[cur]);
        }
        if (half == 0) {
            __syncthreads();             // all warps done reading W half 0
            load_w_half(1);
            CP_COMMIT();
            CP_WAIT_0();
            __syncthreads();
        }
    }

    // ---- epilogue 2: relu(dnorm * acc + bias) -> out ----
#pragma unroll
    for (int i = 0; i < 2; i++) {
        int r0 = warp_m * 32 + i * 16 + gid;
        int node0 = m0 + r0, node1 = node0 + 8;
        float dn0 = g_dnorm[bb * NN + node0];
        float dn1 = g_dnorm[bb * NN + node1];
#pragma unroll
        for (int j = 0; j < 4; j++) {
            int g = warp_n * 32 + j * 8 + tq * 2;
            float b0 = bias[g], b1 = bias[g + 1];
            float2 v0, v1;
            v0.x = fmaxf(dn0 * C[i][j][0] + b0, 0.f);
            v0.y = fmaxf(dn0 * C[i][j][1] + b1, 0.f);
            v1.x = fmaxf(dn1 * C[i][j][2] + b0, 0.f);
            v1.y = fmaxf(dn1 * C[i][j][3] + b1, 0.f);
            *(float2*)(out + ((size_t)(bb * NN + node0)) * FF + g) = v0;
            *(float2*)(out + ((size_t)(bb * NN + node1)) * FF + g) = v1;
        }
    }
}

// ---------------- launch ----------------
extern "C" void kernel_launch(void* const* d_in, const int* in_sizes, int n_in,
                              void* d_out, int out_size) {
    const float* adj  = (const float*)d_in[0];
    const float* x    = (const float*)d_in[1];
    const float* W    = (const float*)d_in[2];
    const float* bias = (const float*)d_in[3];
    float* out = (float*)d_out;

    cudaFuncSetAttribute(fused_kernel, cudaFuncAttributeMaxDynamicSharedMemorySize,
                         FUSED_SMEM);

    deg_kernel<<<(BB * NN) / 8, 256>>>(adj);
    prep_w_kernel<<<16, 256>>>(W);
    prep_h_kernel<<<BB * 8, 256>>>(x);
    fused_kernel<<<BB * 4, 512, FUSED_SMEM>>>(adj, bias, out);
}